// round 4
// baseline (speedup 1.0000x reference)
#include <cuda_runtime.h>

#define N_QUBITS 10
#define N_LAYERS 3
#define BATCH    16384
#define PI_F     3.14159265358979f

// Fused per-(layer,qubit) 2x2 complex unitary U = Rz(g)*Ry(b)*Rx(a).
// g_U[(layer*10+q)*2 + 0] = (u00r, u00i, u01r, u01i)
// g_U[(layer*10+q)*2 + 1] = (u10r, u10i, u11r, u11i)
__device__ float4 g_U[N_LAYERS * N_QUBITS * 2];

__global__ void prep_kernel(const float* __restrict__ w) {
    int i = threadIdx.x;          // 0..29 -> (layer, qubit)
    if (i >= N_LAYERS * N_QUBITS) return;
    float a = w[i * 3 + 0] * 0.5f;
    float b = w[i * 3 + 1] * 0.5f;
    float g = w[i * 3 + 2] * 0.5f;
    float ca, sa, cb, sb, cg, sg;
    sincosf(a, &sa, &ca);
    sincosf(b, &sb, &cb);
    sincosf(g, &sg, &cg);
    // M = Ry * Rx
    float m00r = cb * ca, m00i =  sb * sa;
    float m01r = -sb * ca, m01i = -cb * sa;
    float m10r =  sb * ca, m10i = -cb * sa;
    float m11r =  cb * ca, m11i = -sb * sa;
    // row0 *= (cg - i sg), row1 *= (cg + i sg)
    float4 r0, r1;
    r0.x = cg * m00r + sg * m00i;  r0.y = cg * m00i - sg * m00r;
    r0.z = cg * m01r + sg * m01i;  r0.w = cg * m01i - sg * m01r;
    r1.x = cg * m10r - sg * m10i;  r1.y = cg * m10i + sg * m10r;
    r1.z = cg * m11r - sg * m11i;  r1.w = cg * m11i + sg * m11r;
    g_U[i * 2 + 0] = r0;
    g_U[i * 2 + 1] = r1;
}

// ---------------- gate helpers (state: 32 complex amps per lane) -----------
// amplitude index k (10 bits): bits 0..4 = register index j, bits 5..9 = lane.
// qubit q <-> bit (9-q).

template<int B>
__device__ __forceinline__ void u1q_local(float re[32], float im[32],
                                          float4 r0, float4 r1) {
#pragma unroll
    for (int j = 0; j < 32; j++) {
        if (j & (1 << B)) continue;
        const int j1 = j | (1 << B);
        float ar = re[j],  ai = im[j];
        float br = re[j1], bi = im[j1];
        re[j]  = r0.x * ar - r0.y * ai + r0.z * br - r0.w * bi;
        im[j]  = r0.x * ai + r0.y * ar + r0.z * bi + r0.w * br;
        re[j1] = r1.x * ar - r1.y * ai + r1.z * br - r1.w * bi;
        im[j1] = r1.x * ai + r1.y * ar + r1.z * bi + r1.w * br;
    }
}

template<int LB>
__device__ __forceinline__ void u1q_cross(float re[32], float im[32],
                                          float4 r0, float4 r1, int lane) {
    const bool hi = (lane & (1 << LB)) != 0;
    // mine coeff: hi ? u11 : u00 ; partner coeff: hi ? u10 : u01
    float mr = hi ? r1.z : r0.x;
    float mi = hi ? r1.w : r0.y;
    float pr = hi ? r1.x : r0.z;
    float pi = hi ? r1.y : r0.w;
#pragma unroll
    for (int j = 0; j < 32; j++) {
        float xr = __shfl_xor_sync(0xffffffffu, re[j], 1 << LB);
        float xi = __shfl_xor_sync(0xffffffffu, im[j], 1 << LB);
        float r = re[j], i_ = im[j];
        re[j] = mr * r  - mi * i_ + pr * xr - pi * xi;
        im[j] = mr * i_ + mi * r  + pr * xi + pi * xr;
    }
}

// CNOT: control bit BC/CLB, target bit BT/TLB (all in k-bit space).
template<int BC, int BT>
__device__ __forceinline__ void cnot_ll(float re[32], float im[32]) {
#pragma unroll
    for (int j = 0; j < 32; j++) {
        if (!(j & (1 << BC)) || (j & (1 << BT))) continue;
        const int j1 = j | (1 << BT);
        float t;
        t = re[j]; re[j] = re[j1]; re[j1] = t;
        t = im[j]; im[j] = im[j1]; im[j1] = t;
    }
}

template<int CLB, int BT>
__device__ __forceinline__ void cnot_cl(float re[32], float im[32], int lane) {
    const bool cs = (lane & (1 << CLB)) != 0;
#pragma unroll
    for (int j = 0; j < 32; j++) {
        if (j & (1 << BT)) continue;
        const int j1 = j | (1 << BT);
        if (cs) {
            float t;
            t = re[j]; re[j] = re[j1]; re[j1] = t;
            t = im[j]; im[j] = im[j1]; im[j1] = t;
        }
    }
}

template<int BC, int TLB>
__device__ __forceinline__ void cnot_lc(float re[32], float im[32]) {
#pragma unroll
    for (int j = 0; j < 32; j++) {
        if (!(j & (1 << BC))) continue;
        re[j] = __shfl_xor_sync(0xffffffffu, re[j], 1 << TLB);
        im[j] = __shfl_xor_sync(0xffffffffu, im[j], 1 << TLB);
    }
}

template<int CLB, int TLB>
__device__ __forceinline__ void cnot_cc(float re[32], float im[32], int lane) {
    const bool cs = (lane & (1 << CLB)) != 0;
#pragma unroll
    for (int j = 0; j < 32; j++) {
        float xr = __shfl_xor_sync(0xffffffffu, re[j], 1 << TLB);
        float xi = __shfl_xor_sync(0xffffffffu, im[j], 1 << TLB);
        if (cs) { re[j] = xr; im[j] = xi; }
    }
}

__global__ void __launch_bounds__(256, 2)
vql_kernel(const float* __restrict__ x, float* __restrict__ out) {
    const int warp_id = (blockIdx.x * blockDim.x + threadIdx.x) >> 5;
    const int lane = threadIdx.x & 31;
    if (warp_id >= BATCH) return;
    const int b = warp_id;

    // ---- encoding angles: lane q computes cos/sin(tanh(x_q)*pi/2) ----
    float xin = 0.0f;
    if (lane < N_QUBITS) xin = x[b * N_QUBITS + lane];
    float h = tanhf(xin) * (0.5f * PI_F);
    float cl, sl;
    sincosf(h, &sl, &cl);
    float cq[N_QUBITS], sq[N_QUBITS];
#pragma unroll
    for (int q = 0; q < N_QUBITS; q++) {
        cq[q] = __shfl_sync(0xffffffffu, cl, q);
        sq[q] = __shfl_sync(0xffffffffu, sl, q);
    }

    // ---- init product state directly (real) ----
    // lane bit lb <-> qubit 4-lb ; local bit bb <-> qubit 9-bb
    float lf = 1.0f;
#pragma unroll
    for (int lb = 0; lb < 5; lb++)
        lf *= ((lane >> lb) & 1) ? sq[4 - lb] : cq[4 - lb];

    float re[32], im[32];
    re[0] = lf;
#pragma unroll
    for (int bb = 0; bb < 5; bb++) {
#pragma unroll
        for (int j = 0; j < (1 << bb); j++) {
            float t = re[j];
            re[j]             = t * cq[9 - bb];
            re[j | (1 << bb)] = t * sq[9 - bb];
        }
    }
#pragma unroll
    for (int j = 0; j < 32; j++) im[j] = 0.0f;

    // ---- layers ----
#pragma unroll 1
    for (int layer = 0; layer < N_LAYERS; layer++) {
        const int base = layer * N_QUBITS;

        // CNOT ring: CNOT(i, i+1 mod 10); qubit q <-> bit 9-q
        cnot_cc<4, 3>(re, im, lane);   // i=0: bits 9->8  (lane 4 -> lane 3)
        cnot_cc<3, 2>(re, im, lane);   // i=1
        cnot_cc<2, 1>(re, im, lane);   // i=2
        cnot_cc<1, 0>(re, im, lane);   // i=3
        cnot_cl<0, 4>(re, im, lane);   // i=4: c bit5(lane0), t bit4(local4)
        cnot_ll<4, 3>(re, im);         // i=5
        cnot_ll<3, 2>(re, im);         // i=6
        cnot_ll<2, 1>(re, im);         // i=7
        cnot_ll<1, 0>(re, im);         // i=8
        cnot_lc<0, 4>(re, im);         // i=9: c bit0(local0), t bit9(lane4)

#define GATE_CROSS(i, LB)                                           \
        { float4 r0 = g_U[(base + (i)) * 2 + 0];                    \
          float4 r1 = g_U[(base + (i)) * 2 + 1];                    \
          u1q_cross<LB>(re, im, r0, r1, lane); }
#define GATE_LOCAL(i, B)                                            \
        { float4 r0 = g_U[(base + (i)) * 2 + 0];                    \
          float4 r1 = g_U[(base + (i)) * 2 + 1];                    \
          u1q_local<B>(re, im, r0, r1); }

        GATE_CROSS(0, 4)
        GATE_CROSS(1, 3)
        GATE_CROSS(2, 2)
        GATE_CROSS(3, 1)
        GATE_CROSS(4, 0)
        GATE_LOCAL(5, 4)
        GATE_LOCAL(6, 3)
        GATE_LOCAL(7, 2)
        GATE_LOCAL(8, 1)
        GATE_LOCAL(9, 0)
#undef GATE_CROSS
#undef GATE_LOCAL
    }

    // ---- measurement: <Z_w> = sum_k p_k * (1 - 2*bit(9-w,k)) ----
    float S = 0.0f, S0 = 0.0f, S1 = 0.0f, S2 = 0.0f, S3 = 0.0f, S4 = 0.0f;
#pragma unroll
    for (int j = 0; j < 32; j++) {
        float pj = re[j] * re[j] + im[j] * im[j];
        S += pj;
        if (j & 1)  S0 += pj;
        if (j & 2)  S1 += pj;
        if (j & 4)  S2 += pj;
        if (j & 8)  S3 += pj;
        if (j & 16) S4 += pj;
    }

    float v[N_QUBITS];
    // w = 0..4: lane bit (4-w) gives the sign
    v[0] = ((lane >> 4) & 1) ? -S : S;
    v[1] = ((lane >> 3) & 1) ? -S : S;
    v[2] = ((lane >> 2) & 1) ? -S : S;
    v[3] = ((lane >> 1) & 1) ? -S : S;
    v[4] = ((lane >> 0) & 1) ? -S : S;
    // w = 5..9: local bit (9-w)
    v[5] = S - 2.0f * S4;
    v[6] = S - 2.0f * S3;
    v[7] = S - 2.0f * S2;
    v[8] = S - 2.0f * S1;
    v[9] = S - 2.0f * S0;

#pragma unroll
    for (int w = 0; w < N_QUBITS; w++) {
#pragma unroll
        for (int off = 16; off > 0; off >>= 1)
            v[w] += __shfl_xor_sync(0xffffffffu, v[w], off);
    }

    if (lane == 0) {
#pragma unroll
        for (int w = 0; w < N_QUBITS; w++)
            out[b * N_QUBITS + w] = v[w];
    }
}

extern "C" void kernel_launch(void* const* d_in, const int* in_sizes, int n_in,
                              void* d_out, int out_size) {
    const float* x = (const float*)d_in[0];        // (16384, 10)
    const float* w = (const float*)d_in[1];        // (3, 10, 3)
    float* out = (float*)d_out;                    // (16384, 10)
    prep_kernel<<<1, 32>>>(w);
    const int threads = 256;
    const int blocks = (BATCH * 32) / threads;     // 2048
    vql_kernel<<<blocks, threads>>>(x, out);
}

// round 5
// speedup vs baseline: 1.0899x; 1.0899x over previous
#include <cuda_runtime.h>

typedef unsigned long long ull;

#define N_QUBITS 10
#define N_LAYERS 3
#define BATCH    16384
#define PI_F     3.14159265358979f

// Fused per-(layer,qubit) 2x2 complex unitary U = Rz(g)*Ry(b)*Rx(a).
// g_U[(layer*10+q)*2 + {0,1}] = rows (u00r,u00i,u01r,u01i) / (u10r,u10i,u11r,u11i)
__device__ float4 g_U[N_LAYERS * N_QUBITS * 2];
// Broadcast f32x2 coefficient packs per gate, 12 each:
// [0]=c00r2 [1]=c00i2 [2]=-c00i2 [3]=c01r2 [4]=c01i2 [5]=-c01i2
// [6]=c11r2 [7]=c11i2 [8]=-c11i2 [9]=c10r2 [10]=c10i2 [11]=-c10i2
__device__ ull g_P[N_LAYERS * N_QUBITS * 12];

// ---------------- f32x2 helpers ----------------
__device__ __forceinline__ ull pk(float lo, float hi) {
    ull r; asm("mov.b64 %0, {%1, %2};" : "=l"(r) : "f"(lo), "f"(hi)); return r;
}
__device__ __forceinline__ float getlo(ull v) {
    float a, b; asm("mov.b64 {%0, %1}, %2;" : "=f"(a), "=f"(b) : "l"(v)); return a;
}
__device__ __forceinline__ float gethi(ull v) {
    float a, b; asm("mov.b64 {%0, %1}, %2;" : "=f"(a), "=f"(b) : "l"(v)); return b;
}
__device__ __forceinline__ ull fma2(ull a, ull b, ull c) {
    ull r; asm("fma.rn.f32x2 %0, %1, %2, %3;" : "=l"(r) : "l"(a), "l"(b), "l"(c)); return r;
}
__device__ __forceinline__ ull mul2(ull a, ull b) {
    ull r; asm("mul.rn.f32x2 %0, %1, %2;" : "=l"(r) : "l"(a), "l"(b)); return r;
}
__device__ __forceinline__ ull add2(ull a, ull b) {
    ull r; asm("add.rn.f32x2 %0, %1, %2;" : "=l"(r) : "l"(a), "l"(b)); return r;
}

__global__ void prep_kernel(const float* __restrict__ w) {
    int i = threadIdx.x;          // 0..29 -> (layer, qubit)
    if (i >= N_LAYERS * N_QUBITS) return;
    float a = w[i * 3 + 0] * 0.5f;
    float b = w[i * 3 + 1] * 0.5f;
    float g = w[i * 3 + 2] * 0.5f;
    float ca, sa, cb, sb, cg, sg;
    sincosf(a, &sa, &ca);
    sincosf(b, &sb, &cb);
    sincosf(g, &sg, &cg);
    // M = Ry * Rx
    float m00r = cb * ca, m00i =  sb * sa;
    float m01r = -sb * ca, m01i = -cb * sa;
    float m10r =  sb * ca, m10i = -cb * sa;
    float m11r =  cb * ca, m11i = -sb * sa;
    // row0 *= (cg - i sg), row1 *= (cg + i sg)
    float4 r0, r1;
    r0.x = cg * m00r + sg * m00i;  r0.y = cg * m00i - sg * m00r;
    r0.z = cg * m01r + sg * m01i;  r0.w = cg * m01i - sg * m01r;
    r1.x = cg * m10r - sg * m10i;  r1.y = cg * m10i + sg * m10r;
    r1.z = cg * m11r - sg * m11i;  r1.w = cg * m11i + sg * m11r;
    g_U[i * 2 + 0] = r0;
    g_U[i * 2 + 1] = r1;
    ull* P = g_P + i * 12;
    P[0]  = pk(r0.x, r0.x);  P[1]  = pk(r0.y, r0.y);  P[2]  = pk(-r0.y, -r0.y);
    P[3]  = pk(r0.z, r0.z);  P[4]  = pk(r0.w, r0.w);  P[5]  = pk(-r0.w, -r0.w);
    P[6]  = pk(r1.z, r1.z);  P[7]  = pk(r1.w, r1.w);  P[8]  = pk(-r1.w, -r1.w);
    P[9]  = pk(r1.x, r1.x);  P[10] = pk(r1.y, r1.y);  P[11] = pk(-r1.y, -r1.y);
}

// ---------------- gates on packed state (16 x f32x2 per component) ----------
// amplitude index k (10 bits): bit0 = packed half, bits 1..4 = packed reg p,
// bits 5..9 = lane.  qubit q <-> k-bit (9-q).

template<int LB>
__device__ __forceinline__ void gate_cross(ull reP[16], ull imP[16],
                                           const ull* Pb, int lane) {
    const ull* Pg = Pb + (((lane >> LB) & 1) ? 6 : 0);
    ull mr2  = __ldg(Pg + 0), mi2 = __ldg(Pg + 1), nmi2 = __ldg(Pg + 2);
    ull pr2  = __ldg(Pg + 3), pi2 = __ldg(Pg + 4), npi2 = __ldg(Pg + 5);
#pragma unroll
    for (int p = 0; p < 16; p++) {
        ull xr = __shfl_xor_sync(0xffffffffu, reP[p], 1 << LB);
        ull xi = __shfl_xor_sync(0xffffffffu, imP[p], 1 << LB);
        ull r = reP[p], i = imP[p];
        ull t = mul2(mr2, r); t = fma2(nmi2, i, t);
        t = fma2(pr2, xr, t); t = fma2(npi2, xi, t);
        ull u = mul2(mi2, r); u = fma2(mr2, i, u);
        u = fma2(pi2, xr, u); u = fma2(pr2, xi, u);
        reP[p] = t; imP[p] = u;
    }
}

template<int PB>
__device__ __forceinline__ void gate_local(ull reP[16], ull imP[16],
                                           const ull* Pg) {
    ull c00r = __ldg(Pg + 0), c00i = __ldg(Pg + 1), n00i = __ldg(Pg + 2);
    ull c01r = __ldg(Pg + 3), c01i = __ldg(Pg + 4), n01i = __ldg(Pg + 5);
    ull c11r = __ldg(Pg + 6), c11i = __ldg(Pg + 7), n11i = __ldg(Pg + 8);
    ull c10r = __ldg(Pg + 9), c10i = __ldg(Pg + 10), n10i = __ldg(Pg + 11);
#pragma unroll
    for (int p = 0; p < 16; p++) {
        if (p & (1 << PB)) continue;
        const int p1 = p | (1 << PB);
        ull ar = reP[p], ai = imP[p], br = reP[p1], bi = imP[p1];
        ull t;
        t = mul2(c00r, ar); t = fma2(n00i, ai, t); t = fma2(c01r, br, t); t = fma2(n01i, bi, t); reP[p]  = t;
        t = mul2(c00i, ar); t = fma2(c00r, ai, t); t = fma2(c01i, br, t); t = fma2(c01r, bi, t); imP[p]  = t;
        t = mul2(c10r, ar); t = fma2(n10i, ai, t); t = fma2(c11r, br, t); t = fma2(n11i, bi, t); reP[p1] = t;
        t = mul2(c10i, ar); t = fma2(c10r, ai, t); t = fma2(c11i, br, t); t = fma2(c11r, bi, t); imP[p1] = t;
    }
}

// Gate on k-bit 0 (qubit 9): combines packed halves -> scalar path.
__device__ __forceinline__ void gate_bit0(ull reP[16], ull imP[16],
                                          float4 r0, float4 r1) {
#pragma unroll
    for (int p = 0; p < 16; p++) {
        float ar = getlo(reP[p]), br = gethi(reP[p]);
        float ai = getlo(imP[p]), bi = gethi(imP[p]);
        float nr0 = r0.x * ar - r0.y * ai + r0.z * br - r0.w * bi;
        float ni0 = r0.x * ai + r0.y * ar + r0.z * bi + r0.w * br;
        float nr1 = r1.x * ar - r1.y * ai + r1.z * br - r1.w * bi;
        float ni1 = r1.x * ai + r1.y * ar + r1.z * bi + r1.w * br;
        reP[p] = pk(nr0, nr1); imP[p] = pk(ni0, ni1);
    }
}

__device__ __forceinline__ float gelem(const ull* P, int j) {
    return (j & 1) ? gethi(P[j >> 1]) : getlo(P[j >> 1]);
}

__global__ void __launch_bounds__(256, 2)
vql_kernel(const float* __restrict__ x, float* __restrict__ out) {
    const int warp_id = (blockIdx.x * blockDim.x + threadIdx.x) >> 5;
    const int lane = threadIdx.x & 31;
    if (warp_id >= BATCH) return;
    const int b = warp_id;

    // ---- encoding angles ----
    float xin = 0.0f;
    if (lane < N_QUBITS) xin = x[b * N_QUBITS + lane];
    float h = tanhf(xin) * (0.5f * PI_F);
    float cl, sl;
    sincosf(h, &sl, &cl);
    float cq[N_QUBITS], sq[N_QUBITS];
#pragma unroll
    for (int q = 0; q < N_QUBITS; q++) {
        cq[q] = __shfl_sync(0xffffffffu, cl, q);
        sq[q] = __shfl_sync(0xffffffffu, sl, q);
    }

    // ---- init product state (real) ----
    float lf = 1.0f;
#pragma unroll
    for (int lb = 0; lb < 5; lb++)
        lf *= ((lane >> lb) & 1) ? sq[4 - lb] : cq[4 - lb];

    float bp[16];
    bp[0] = lf;
#pragma unroll
    for (int pb = 0; pb < 4; pb++) {          // p-bit pb <-> qubit 8-pb
#pragma unroll
        for (int t = 0; t < (1 << pb); t++) {
            float v = bp[t];
            bp[t]              = v * cq[8 - pb];
            bp[t | (1 << pb)]  = v * sq[8 - pb];
        }
    }
    ull reP[16], imP[16];
#pragma unroll
    for (int p = 0; p < 16; p++) {
        reP[p] = pk(bp[p] * cq[9], bp[p] * sq[9]);   // half <-> qubit 9
        imP[p] = 0ull;
    }

    // gather constants for the fused CNOT-ring permutation
    const int par  = __popc(lane) & 1;
    const int srcE = lane ^ (lane >> 1);
    const int srcO = srcE ^ 24;

    // ---- layers ----
#pragma unroll 1
    for (int layer = 0; layer < N_LAYERS; layer++) {
        const ull* PL = g_P + layer * N_QUBITS * 12;

        // Fused CNOT ring (10 CNOTs == one linear-GF(2) index permutation):
        // new[k'] = old[k], k_b = k'_b^k'_{b+1} (b<=7), k_8=k'_8^k'_9^k'_0,
        // k_9=k'_9^k'_0.
        {
            float nr[32];
#pragma unroll
            for (int jp = 0; jp < 32; jp++) {
                const int jA = (jp ^ (jp >> 1)) & 31;
                float v = par ? gelem(reP, jA ^ 16) : gelem(reP, jA);
                nr[jp] = __shfl_sync(0xffffffffu, v, (jp & 1) ? srcO : srcE);
            }
#pragma unroll
            for (int p = 0; p < 16; p++) reP[p] = pk(nr[2 * p], nr[2 * p + 1]);
            float ni[32];
#pragma unroll
            for (int jp = 0; jp < 32; jp++) {
                const int jA = (jp ^ (jp >> 1)) & 31;
                float v = par ? gelem(imP, jA ^ 16) : gelem(imP, jA);
                ni[jp] = __shfl_sync(0xffffffffu, v, (jp & 1) ? srcO : srcE);
            }
#pragma unroll
            for (int p = 0; p < 16; p++) imP[p] = pk(ni[2 * p], ni[2 * p + 1]);
        }

        // gates q = 0..9
        gate_cross<4>(reP, imP, PL + 0 * 12, lane);   // q=0 (k bit 9)
        gate_cross<3>(reP, imP, PL + 1 * 12, lane);   // q=1
        gate_cross<2>(reP, imP, PL + 2 * 12, lane);   // q=2
        gate_cross<1>(reP, imP, PL + 3 * 12, lane);   // q=3
        gate_cross<0>(reP, imP, PL + 4 * 12, lane);   // q=4 (k bit 5)
        gate_local<3>(reP, imP, PL + 5 * 12);         // q=5 (k bit 4)
        gate_local<2>(reP, imP, PL + 6 * 12);         // q=6
        gate_local<1>(reP, imP, PL + 7 * 12);         // q=7
        gate_local<0>(reP, imP, PL + 8 * 12);         // q=8 (k bit 1)
        {
            float4 r0 = g_U[(layer * N_QUBITS + 9) * 2 + 0];
            float4 r1 = g_U[(layer * N_QUBITS + 9) * 2 + 1];
            gate_bit0(reP, imP, r0, r1);              // q=9 (k bit 0)
        }
    }

    // ---- measurement ----
    ull Sa = 0ull, A1 = 0ull, A2 = 0ull, A3 = 0ull, A4 = 0ull;
#pragma unroll
    for (int p = 0; p < 16; p++) {
        ull pp = mul2(reP[p], reP[p]);
        pp = fma2(imP[p], imP[p], pp);
        Sa = add2(Sa, pp);
        if (p & 1) A1 = add2(A1, pp);
        if (p & 2) A2 = add2(A2, pp);
        if (p & 4) A3 = add2(A3, pp);
        if (p & 8) A4 = add2(A4, pp);
    }
    float S  = getlo(Sa) + gethi(Sa);
    float S0 = gethi(Sa);                       // k bit0 set
    float S1 = getlo(A1) + gethi(A1);
    float S2 = getlo(A2) + gethi(A2);
    float S3 = getlo(A3) + gethi(A3);
    float S4 = getlo(A4) + gethi(A4);

    float v[N_QUBITS];
    v[0] = ((lane >> 4) & 1) ? -S : S;
    v[1] = ((lane >> 3) & 1) ? -S : S;
    v[2] = ((lane >> 2) & 1) ? -S : S;
    v[3] = ((lane >> 1) & 1) ? -S : S;
    v[4] = ((lane >> 0) & 1) ? -S : S;
    v[5] = S - 2.0f * S4;
    v[6] = S - 2.0f * S3;
    v[7] = S - 2.0f * S2;
    v[8] = S - 2.0f * S1;
    v[9] = S - 2.0f * S0;

#pragma unroll
    for (int w = 0; w < N_QUBITS; w++) {
#pragma unroll
        for (int off = 16; off > 0; off >>= 1)
            v[w] += __shfl_xor_sync(0xffffffffu, v[w], off);
    }

    if (lane == 0) {
#pragma unroll
        for (int w = 0; w < N_QUBITS; w++)
            out[b * N_QUBITS + w] = v[w];
    }
}

extern "C" void kernel_launch(void* const* d_in, const int* in_sizes, int n_in,
                              void* d_out, int out_size) {
    const float* x = (const float*)d_in[0];        // (16384, 10)
    const float* w = (const float*)d_in[1];        // (3, 10, 3)
    float* out = (float*)d_out;                    // (16384, 10)
    prep_kernel<<<1, 32>>>(w);
    const int threads = 256;
    const int blocks = (BATCH * 32) / threads;     // 2048
    vql_kernel<<<blocks, threads>>>(x, out);
}

// round 10
// speedup vs baseline: 1.3506x; 1.2392x over previous
#include <cuda_runtime.h>

typedef unsigned long long ull;

#define N_QUBITS 10
#define N_LAYERS 3
#define BATCH    16384
#define PI_F     3.14159265358979f

#define NPACK (N_LAYERS * N_QUBITS * 12)   // 360 packed ulls

// Fused per-(layer,qubit) 2x2 complex unitary U = Rz(g)*Ry(b)*Rx(a),
// stored as broadcast f32x2 coefficient packs, 12 ull per gate.
// q = 0..8: [0]=c00r2 [1]=c00i2 [2]=-c00i2 [3]=c01r2 [4]=c01i2 [5]=-c01i2
//           [6]=c11r2 [7]=c11i2 [8]=-c11i2 [9]=c10r2 [10]=c10i2 [11]=-c10i2
// q = 9 (packed bit, half-swap form):
//           [0]=C1r [1]=C1i [2]=-C1i [3]=C2r [4]=C2i [5]=-C2i
//           where C1=(u00,u11) lo/hi, C2=(u01,u10) lo/hi.
__device__ ull g_P[NPACK];

// ---------------- f32x2 helpers ----------------
__device__ __forceinline__ ull pk(float lo, float hi) {
    ull r; asm("mov.b64 %0, {%1, %2};" : "=l"(r) : "f"(lo), "f"(hi)); return r;
}
__device__ __forceinline__ float getlo(ull v) {
    float a, b; asm("mov.b64 {%0, %1}, %2;" : "=f"(a), "=f"(b) : "l"(v)); return a;
}
__device__ __forceinline__ float gethi(ull v) {
    float a, b; asm("mov.b64 {%0, %1}, %2;" : "=f"(a), "=f"(b) : "l"(v)); return b;
}
__device__ __forceinline__ ull swap2(ull v) {
    float a, b; asm("mov.b64 {%0, %1}, %2;" : "=f"(a), "=f"(b) : "l"(v));
    ull r; asm("mov.b64 %0, {%1, %2};" : "=l"(r) : "f"(b), "f"(a)); return r;
}
__device__ __forceinline__ ull fma2(ull a, ull b, ull c) {
    ull r; asm("fma.rn.f32x2 %0, %1, %2, %3;" : "=l"(r) : "l"(a), "l"(b), "l"(c)); return r;
}
__device__ __forceinline__ ull mul2(ull a, ull b) {
    ull r; asm("mul.rn.f32x2 %0, %1, %2;" : "=l"(r) : "l"(a), "l"(b)); return r;
}
__device__ __forceinline__ ull add2(ull a, ull b) {
    ull r; asm("add.rn.f32x2 %0, %1, %2;" : "=l"(r) : "l"(a), "l"(b)); return r;
}

__global__ void prep_kernel(const float* __restrict__ w) {
    int i = threadIdx.x;          // 0..29 -> (layer, qubit)
    if (i >= N_LAYERS * N_QUBITS) return;
    float a = w[i * 3 + 0] * 0.5f;
    float b = w[i * 3 + 1] * 0.5f;
    float g = w[i * 3 + 2] * 0.5f;
    float ca, sa, cb, sb, cg, sg;
    sincosf(a, &sa, &ca);
    sincosf(b, &sb, &cb);
    sincosf(g, &sg, &cg);
    // M = Ry * Rx
    float m00r = cb * ca, m00i =  sb * sa;
    float m01r = -sb * ca, m01i = -cb * sa;
    float m10r =  sb * ca, m10i = -cb * sa;
    float m11r =  cb * ca, m11i = -sb * sa;
    // row0 *= (cg - i sg), row1 *= (cg + i sg)
    float4 r0, r1;
    r0.x = cg * m00r + sg * m00i;  r0.y = cg * m00i - sg * m00r;
    r0.z = cg * m01r + sg * m01i;  r0.w = cg * m01i - sg * m01r;
    r1.x = cg * m10r - sg * m10i;  r1.y = cg * m10i + sg * m10r;
    r1.z = cg * m11r - sg * m11i;  r1.w = cg * m11i + sg * m11r;
    ull* P = g_P + i * 12;
    if ((i % N_QUBITS) == 9) {
        // half-swap coefficient packs: C1=(u00,u11), C2=(u01,u10)
        P[0] = pk(r0.x, r1.z);   P[1] = pk(r0.y, r1.w);   P[2] = pk(-r0.y, -r1.w);
        P[3] = pk(r0.z, r1.x);   P[4] = pk(r0.w, r1.y);   P[5] = pk(-r0.w, -r1.y);
        P[6] = 0; P[7] = 0; P[8] = 0; P[9] = 0; P[10] = 0; P[11] = 0;
    } else {
        P[0]  = pk(r0.x, r0.x);  P[1]  = pk(r0.y, r0.y);  P[2]  = pk(-r0.y, -r0.y);
        P[3]  = pk(r0.z, r0.z);  P[4]  = pk(r0.w, r0.w);  P[5]  = pk(-r0.w, -r0.w);
        P[6]  = pk(r1.z, r1.z);  P[7]  = pk(r1.w, r1.w);  P[8]  = pk(-r1.w, -r1.w);
        P[9]  = pk(r1.x, r1.x);  P[10] = pk(r1.y, r1.y);  P[11] = pk(-r1.y, -r1.y);
    }
}

// ---------------- gates on packed state (16 x f32x2 per component) ----------
// amplitude index k (10 bits): bit0 = packed half, bits 1..4 = packed reg p,
// bits 5..9 = lane.  qubit q <-> k-bit (9-q).

template<int LB>
__device__ __forceinline__ void gate_cross(ull reP[16], ull imP[16],
                                           const ull* Pb, int lane) {
    const ull* Pg = Pb + (((lane >> LB) & 1) ? 6 : 0);
    ull mr2  = Pg[0], mi2 = Pg[1], nmi2 = Pg[2];
    ull pr2  = Pg[3], pi2 = Pg[4], npi2 = Pg[5];
#pragma unroll
    for (int p = 0; p < 16; p++) {
        ull xr = __shfl_xor_sync(0xffffffffu, reP[p], 1 << LB);
        ull xi = __shfl_xor_sync(0xffffffffu, imP[p], 1 << LB);
        ull r = reP[p], i = imP[p];
        ull t = mul2(mr2, r); t = fma2(nmi2, i, t);
        t = fma2(pr2, xr, t); t = fma2(npi2, xi, t);
        ull u = mul2(mi2, r); u = fma2(mr2, i, u);
        u = fma2(pi2, xr, u); u = fma2(pr2, xi, u);
        reP[p] = t; imP[p] = u;
    }
}

template<int PB>
__device__ __forceinline__ void gate_local(ull reP[16], ull imP[16],
                                           const ull* Pg) {
    ull c00r = Pg[0], c00i = Pg[1], n00i = Pg[2];
    ull c01r = Pg[3], c01i = Pg[4], n01i = Pg[5];
    ull c11r = Pg[6], c11i = Pg[7], n11i = Pg[8];
    ull c10r = Pg[9], c10i = Pg[10], n10i = Pg[11];
#pragma unroll
    for (int p = 0; p < 16; p++) {
        if (p & (1 << PB)) continue;
        const int p1 = p | (1 << PB);
        ull ar = reP[p], ai = imP[p], br = reP[p1], bi = imP[p1];
        ull t;
        t = mul2(c00r, ar); t = fma2(n00i, ai, t); t = fma2(c01r, br, t); t = fma2(n01i, bi, t); reP[p]  = t;
        t = mul2(c00i, ar); t = fma2(c00r, ai, t); t = fma2(c01i, br, t); t = fma2(c01r, bi, t); imP[p]  = t;
        t = mul2(c10r, ar); t = fma2(n10i, ai, t); t = fma2(c11r, br, t); t = fma2(n11i, bi, t); reP[p1] = t;
        t = mul2(c10i, ar); t = fma2(c10r, ai, t); t = fma2(c11i, br, t); t = fma2(c11r, bi, t); imP[p1] = t;
    }
}

// Gate on k-bit 0 (qubit 9): half-swap f32x2 form.
__device__ __forceinline__ void gate_bit0(ull reP[16], ull imP[16],
                                          const ull* Pg) {
    ull C1r = Pg[0], C1i = Pg[1], nC1i = Pg[2];
    ull C2r = Pg[3], C2i = Pg[4], nC2i = Pg[5];
#pragma unroll
    for (int p = 0; p < 16; p++) {
        ull vr = reP[p], vi = imP[p];
        ull sr = swap2(vr), si = swap2(vi);
        ull t = mul2(C1r, vr); t = fma2(nC1i, vi, t);
        t = fma2(C2r, sr, t);  t = fma2(nC2i, si, t);
        ull u = mul2(C1i, vr); u = fma2(C1r, vi, u);
        u = fma2(C2i, sr, u);  u = fma2(C2r, si, u);
        reP[p] = t; imP[p] = u;
    }
}

__device__ __forceinline__ float gelem(const ull* P, int j) {
    return (j & 1) ? gethi(P[j >> 1]) : getlo(P[j >> 1]);
}

__global__ void __launch_bounds__(256, 2)
vql_kernel(const float* __restrict__ x, float* __restrict__ out) {
    __shared__ ull sP[NPACK];
    for (int t = threadIdx.x; t < NPACK; t += blockDim.x) sP[t] = g_P[t];
    __syncthreads();

    const int warp_id = (blockIdx.x * blockDim.x + threadIdx.x) >> 5;
    const int lane = threadIdx.x & 31;
    if (warp_id >= BATCH) return;
    const int b = warp_id;

    // ---- encoding angles ----
    float xin = 0.0f;
    if (lane < N_QUBITS) xin = x[b * N_QUBITS + lane];
    float h = tanhf(xin) * (0.5f * PI_F);
    float cl, sl;
    sincosf(h, &sl, &cl);
    float cq[N_QUBITS], sq[N_QUBITS];
#pragma unroll
    for (int q = 0; q < N_QUBITS; q++) {
        cq[q] = __shfl_sync(0xffffffffu, cl, q);
        sq[q] = __shfl_sync(0xffffffffu, sl, q);
    }

    // ---- init product state (real) ----
    float lf = 1.0f;
#pragma unroll
    for (int lb = 0; lb < 5; lb++)
        lf *= ((lane >> lb) & 1) ? sq[4 - lb] : cq[4 - lb];

    float bp[16];
    bp[0] = lf;
#pragma unroll
    for (int pb = 0; pb < 4; pb++) {          // p-bit pb <-> qubit 8-pb
#pragma unroll
        for (int t = 0; t < (1 << pb); t++) {
            float v = bp[t];
            bp[t]              = v * cq[8 - pb];
            bp[t | (1 << pb)]  = v * sq[8 - pb];
        }
    }
    ull reP[16], imP[16];
#pragma unroll
    for (int p = 0; p < 16; p++) {
        reP[p] = pk(bp[p] * cq[9], bp[p] * sq[9]);   // half <-> qubit 9
        imP[p] = 0ull;
    }

    // gather constants for the fused CNOT-ring permutation
    const int par  = __popc(lane) & 1;
    const int srcE = lane ^ (lane >> 1);
    const int srcO = srcE ^ 24;

    // ---- layers ----
#pragma unroll 1
    for (int layer = 0; layer < N_LAYERS; layer++) {
        const ull* PL = sP + layer * N_QUBITS * 12;

        // Fused CNOT ring (10 CNOTs == one linear-GF(2) index permutation):
        // new[k'] = old[k], k_b = k'_b^k'_{b+1} (b<=7), k_8=k'_8^k'_9^k'_0,
        // k_9=k'_9^k'_0.
        {
            float nr[32];
#pragma unroll
            for (int jp = 0; jp < 32; jp++) {
                const int jA = (jp ^ (jp >> 1)) & 31;
                float v = par ? gelem(reP, jA ^ 16) : gelem(reP, jA);
                nr[jp] = __shfl_sync(0xffffffffu, v, (jp & 1) ? srcO : srcE);
            }
#pragma unroll
            for (int p = 0; p < 16; p++) reP[p] = pk(nr[2 * p], nr[2 * p + 1]);
            if (layer != 0) {   // layer 0: imaginary part is identically zero
                float ni[32];
#pragma unroll
                for (int jp = 0; jp < 32; jp++) {
                    const int jA = (jp ^ (jp >> 1)) & 31;
                    float v = par ? gelem(imP, jA ^ 16) : gelem(imP, jA);
                    ni[jp] = __shfl_sync(0xffffffffu, v, (jp & 1) ? srcO : srcE);
                }
#pragma unroll
                for (int p = 0; p < 16; p++) imP[p] = pk(ni[2 * p], ni[2 * p + 1]);
            }
        }

        // gates q = 0..9
        gate_cross<4>(reP, imP, PL + 0 * 12, lane);   // q=0 (k bit 9)
        gate_cross<3>(reP, imP, PL + 1 * 12, lane);   // q=1
        gate_cross<2>(reP, imP, PL + 2 * 12, lane);   // q=2
        gate_cross<1>(reP, imP, PL + 3 * 12, lane);   // q=3
        gate_cross<0>(reP, imP, PL + 4 * 12, lane);   // q=4 (k bit 5)
        gate_local<3>(reP, imP, PL + 5 * 12);         // q=5 (k bit 4)
        gate_local<2>(reP, imP, PL + 6 * 12);         // q=6
        gate_local<1>(reP, imP, PL + 7 * 12);         // q=7
        gate_local<0>(reP, imP, PL + 8 * 12);         // q=8 (k bit 1)
        gate_bit0(reP, imP, PL + 9 * 12);             // q=9 (k bit 0)
    }

    // ---- measurement ----
    ull Sa = 0ull, A1 = 0ull, A2 = 0ull, A3 = 0ull, A4 = 0ull;
#pragma unroll
    for (int p = 0; p < 16; p++) {
        ull pp = mul2(reP[p], reP[p]);
        pp = fma2(imP[p], imP[p], pp);
        Sa = add2(Sa, pp);
        if (p & 1) A1 = add2(A1, pp);
        if (p & 2) A2 = add2(A2, pp);
        if (p & 4) A3 = add2(A3, pp);
        if (p & 8) A4 = add2(A4, pp);
    }
    float S  = getlo(Sa) + gethi(Sa);
    float S0 = gethi(Sa);                       // k bit0 set
    float S1 = getlo(A1) + gethi(A1);
    float S2 = getlo(A2) + gethi(A2);
    float S3 = getlo(A3) + gethi(A3);
    float S4 = getlo(A4) + gethi(A4);

    float v[N_QUBITS];
    v[0] = ((lane >> 4) & 1) ? -S : S;
    v[1] = ((lane >> 3) & 1) ? -S : S;
    v[2] = ((lane >> 2) & 1) ? -S : S;
    v[3] = ((lane >> 1) & 1) ? -S : S;
    v[4] = ((lane >> 0) & 1) ? -S : S;
    v[5] = S - 2.0f * S4;
    v[6] = S - 2.0f * S3;
    v[7] = S - 2.0f * S2;
    v[8] = S - 2.0f * S1;
    v[9] = S - 2.0f * S0;

#pragma unroll
    for (int w = 0; w < N_QUBITS; w++) {
#pragma unroll
        for (int off = 16; off > 0; off >>= 1)
            v[w] += __shfl_xor_sync(0xffffffffu, v[w], off);
    }

    if (lane == 0) {
#pragma unroll
        for (int w = 0; w < N_QUBITS; w++)
            out[b * N_QUBITS + w] = v[w];
    }
}

extern "C" void kernel_launch(void* const* d_in, const int* in_sizes, int n_in,
                              void* d_out, int out_size) {
    const float* x = (const float*)d_in[0];        // (16384, 10)
    const float* w = (const float*)d_in[1];        // (3, 10, 3)
    float* out = (float*)d_out;                    // (16384, 10)
    prep_kernel<<<1, 32>>>(w);
    const int threads = 256;
    const int blocks = (BATCH * 32) / threads;     // 2048
    vql_kernel<<<blocks, threads>>>(x, out);
}